// round 10
// baseline (speedup 1.0000x reference)
#include <cuda_runtime.h>
#include <cstdint>
#include <cstddef>

// ===================== problem constants =====================
static constexpr int NP      = 50000;     // particles
static constexpr int NPAD    = 50048;     // padded to 782*64
static constexpr int EDG     = 800000;
static constexpr int CAP     = 64;        // slots per receiver (Poisson(16) tail-safe)
static constexpr int KDIM    = 512;       // folded contraction dim: 8 taps * 64 ch
static constexpr int OUTC    = 64;
static constexpr int PD      = 8;         // phase1 cp.async pipeline depth

// ===================== device scratch (no allocs allowed) =====================
__device__ int    g_deg[NPAD];
__device__ int    g_slotS[(size_t)NPAD * CAP];        // sender per slot
__device__ float4 g_wp[(size_t)NPAD * CAP * 2];       // folded weights, 2 float4 per slot
__device__ float  g_Ahi[(size_t)NPAD * KDIM];         // tf32-hi folded aggregate [NPAD][512]
__device__ float  g_Alo[(size_t)NPAD * KDIM];         // tf32-lo residual
__device__ float  g_Bhi[OUTC * KDIM];                 // tf32-hi folded kernel, [n][k]
__device__ float  g_Blo[OUTC * KDIM];                 // tf32-lo residual,      [n][k]

// ===================== helpers =====================
__device__ __forceinline__ uint32_t f2tf32(float x) {
    uint32_t r;
    asm("cvt.rna.tf32.f32 %0, %1;" : "=r"(r) : "f"(x));
    return r;
}

__device__ __forceinline__ uint32_t smem_u32(const void* p) {
    return (uint32_t)__cvta_generic_to_shared(p);
}

__device__ __forceinline__ void mma8(float* c, const uint32_t* a, const uint32_t* b) {
    asm volatile(
        "mma.sync.aligned.m16n8k8.row.col.f32.tf32.tf32.f32 "
        "{%0,%1,%2,%3}, {%4,%5,%6,%7}, {%8,%9}, {%0,%1,%2,%3};"
        : "+f"(c[0]), "+f"(c[1]), "+f"(c[2]), "+f"(c[3])
        : "r"(a[0]), "r"(a[1]), "r"(a[2]), "r"(a[3]), "r"(b[0]), "r"(b[1]));
}

__device__ __forceinline__ void ldsm4(uint32_t* r, uint32_t addr) {
    asm volatile("ldmatrix.sync.aligned.m8n8.x4.shared.b16 {%0,%1,%2,%3}, [%4];"
                 : "=r"(r[0]), "=r"(r[1]), "=r"(r[2]), "=r"(r[3]) : "r"(addr));
}

// ===================== kernel 1: zero degree counters + build folded B =====================
// B layout [n][k], tf32 hi/lo split. k = t*64+i, t = x*4+y with x in {0,1}.
__global__ void k_prep(const float* __restrict__ ker) {
    int i = blockIdx.x * blockDim.x + threadIdx.x;
    if (i < NPAD) g_deg[i] = 0;
    if (i < KDIM * OUTC) {
        int n = i / KDIM;
        int k = i % KDIM;
        int t = k / 64, ic = k % 64;
        int x = t / 4, y = t % 4;
        float v;
        if (y < 2) v = ker[(((x * 2 + y) * 64 + ic) * 64) + n];
        else       v = -ker[((((3 - x) * 2 + (3 - y)) * 64 + ic) * 64) + n];
        uint32_t hb = f2tf32(v);
        float hi = __uint_as_float(hb);
        uint32_t lb = f2tf32(v - hi);
        g_Bhi[n * KDIM + k] = hi;
        g_Blo[n * KDIM + k] = __uint_as_float(lb);
    }
}

// ===================== kernel 2: bucket edges + precompute folded weights =====================
__global__ void k_fill(const int* __restrict__ recv, const int* __restrict__ snd,
                       const float* __restrict__ rp, const float* __restrict__ ws_p) {
    int e = blockIdx.x * blockDim.x + threadIdx.x;
    if (e >= EDG) return;
    int r = recv[e];
    int slot = atomicAdd(&g_deg[r], 1);
    if (slot >= CAP) return;

    float inv_ws = 1.0f / (*ws_p);
    float2 p = ((const float2*)rp)[e];
    float ux = fminf(fmaxf(p.x * inv_ws, -1.f), 1.f);
    float uy = fminf(fmaxf(p.y * inv_ws, -1.f), 1.f);
    float gx = (ux + 1.f) * 1.5f;
    float gy = (uy + 1.f) * 1.5f;
    float x0 = fminf(fmaxf(floorf(gx), 0.f), 2.f);
    float y0 = fminf(fmaxf(floorf(gy), 0.f), 2.f);
    float fx = gx - x0, fy = gy - y0;
    int x0i = (int)x0, y0i = (int)y0;
    float r2 = ux * ux + uy * uy;
    float win = fmaxf(1.f - r2, 0.f);
    win = win * win * win;

    float wx[4], wy[4];
    #pragma unroll
    for (int j = 0; j < 4; j++) {
        wx[j] = (j == x0i) ? (1.f - fx) * win : ((j == x0i + 1) ? fx * win : 0.f);
        wy[j] = (j == y0i) ? (1.f - fy)       : ((j == y0i + 1) ? fy       : 0.f);
    }
    float wf[8];
    #pragma unroll
    for (int f = 0; f < 8; f++) {
        int xf = f >> 2, yf = f & 3;
        wf[f] = wx[xf] * wy[yf] - wx[3 - xf] * wy[3 - yf];
    }
    size_t si = (size_t)r * CAP + slot;
    g_slotS[si] = snd[e];
    g_wp[si * 2 + 0] = make_float4(wf[0], wf[1], wf[2], wf[3]);
    g_wp[si * 2 + 1] = make_float4(wf[4], wf[5], wf[6], wf[7]);
}

// ===================== kernel 3: per-receiver aggregation, cp.async pipeline, unroll-4 =====================
// Output: A split into tf32 hi/lo at store time (bit-identical to splitting in GEMM).
__global__ void __launch_bounds__(64) k_phase1(const float* __restrict__ feat) {
    __shared__ float sFeat[2][PD][64];
    __shared__ float sW[2][PD][8];

    int warp = threadIdx.x >> 5, lane = threadIdx.x & 31;
    int r = blockIdx.x * 2 + warp;          // grid = NPAD/2 exactly
    int nd = min(g_deg[r], CAP);            // uniform across warp
    size_t base = (size_t)r * CAP;

    int sl = (lane < nd)      ? g_slotS[base + lane]      : 0;
    int sh = (32 + lane < nd) ? g_slotS[base + 32 + lane] : 0;

    float acc[16];
    #pragma unroll
    for (int j = 0; j < 16; j++) acc[j] = 0.f;

    #define ISSUE(e) do {                                                        \
        int _e = (e);                                                            \
        if (_e < nd) {                                                           \
            int _j = _e & (PD - 1);                                              \
            int _s = __shfl_sync(0xFFFFFFFFu, (_e < 32) ? sl : sh, _e & 31);     \
            if (lane < 16) {                                                     \
                const float4* _src = (const float4*)(feat + (size_t)_s * 64) + lane; \
                uint32_t _dst = smem_u32(&sFeat[warp][_j][lane * 4]);            \
                asm volatile("cp.async.ca.shared.global [%0], [%1], 16;"         \
                             :: "r"(_dst), "l"(_src) : "memory");                \
            } else if (lane < 18) {                                              \
                const float4* _src = &g_wp[(base + _e) * 2 + (lane - 16)];       \
                uint32_t _dst = smem_u32(&sW[warp][_j][(lane - 16) * 4]);        \
                asm volatile("cp.async.ca.shared.global [%0], [%1], 16;"         \
                             :: "r"(_dst), "l"(_src) : "memory");                \
            }                                                                    \
        }                                                                        \
        asm volatile("cp.async.commit_group;" ::: "memory");                     \
    } while (0)

    #define CONSUME(e) do {                                                      \
        int _jb = (e) & (PD - 1);                                                \
        float2 f  = *(const float2*)&sFeat[warp][_jb][lane * 2];                 \
        float4 w0 = *(const float4*)&sW[warp][_jb][0];                           \
        float4 w1 = *(const float4*)&sW[warp][_jb][4];                           \
        acc[0]  += w0.x * f.x;  acc[1]  += w0.x * f.y;                           \
        acc[2]  += w0.y * f.x;  acc[3]  += w0.y * f.y;                           \
        acc[4]  += w0.z * f.x;  acc[5]  += w0.z * f.y;                           \
        acc[6]  += w0.w * f.x;  acc[7]  += w0.w * f.y;                           \
        acc[8]  += w1.x * f.x;  acc[9]  += w1.x * f.y;                           \
        acc[10] += w1.y * f.x;  acc[11] += w1.y * f.y;                           \
        acc[12] += w1.z * f.x;  acc[13] += w1.z * f.y;                           \
        acc[14] += w1.w * f.x;  acc[15] += w1.w * f.y;                           \
    } while (0)

    #pragma unroll
    for (int j = 0; j < PD; j++) ISSUE(j);

    int e = 0;
    for (; e + 3 < nd; e += 4) {
        asm volatile("cp.async.wait_group %0;" :: "n"(PD - 4) : "memory");
        __syncwarp();
        CONSUME(e);
        CONSUME(e + 1);
        CONSUME(e + 2);
        CONSUME(e + 3);
        __syncwarp();
        ISSUE(e + PD);
        ISSUE(e + PD + 1);
        ISSUE(e + PD + 2);
        ISSUE(e + PD + 3);
    }
    if (e < nd) {
        asm volatile("cp.async.wait_group 0;" ::: "memory");
        __syncwarp();
        for (; e < nd; e++) CONSUME(e);
    }
    #undef ISSUE
    #undef CONSUME

    float* dhi = g_Ahi + (size_t)r * KDIM + 2 * lane;
    float* dlo = g_Alo + (size_t)r * KDIM + 2 * lane;
    #pragma unroll
    for (int t = 0; t < 8; t++) {
        float v0 = acc[2 * t], v1 = acc[2 * t + 1];
        float h0 = __uint_as_float(f2tf32(v0));
        float h1 = __uint_as_float(f2tf32(v1));
        float l0 = __uint_as_float(f2tf32(v0 - h0));
        float l1 = __uint_as_float(f2tf32(v1 - h1));
        *(float2*)(dhi + t * 64) = make_float2(h0, h1);
        *(float2*)(dlo + t * 64) = make_float2(l0, l1);
    }
}

// ===================== kernel 4: tf32 mma GEMM, 3-stage cp.async multistage =====================
// out[NPAD(64/CTA), 64] = A[., 512] @ B^T (B stored [n][k]) + bias
// 8 warps as 2(M) x 4(N); warp: 32 rows x 16 cols; KC=32, 16 chunks, 3 smem stages
static constexpr int KC  = 32;
static constexpr int AST = 36;                 // smem row stride (floats), conflict-free
static constexpr int F_AHI = 0;                // per-stage float offsets
static constexpr int F_ALO = 2304;             // 64*36
static constexpr int F_BHI = 4608;
static constexpr int F_BLO = 6912;
static constexpr int F_BUF = 9216;             // floats per stage (36 KB)
static constexpr int NSTG  = 3;
static constexpr int NCH   = KDIM / KC;        // 16 chunks
static constexpr int GEMM_SMEM = NSTG * F_BUF * 4;   // 110592 bytes

__global__ void __launch_bounds__(256, 2) k_gemm(const float* __restrict__ bias,
                                                 float* __restrict__ out) {
    extern __shared__ float sm[];

    int tid = threadIdx.x;
    int warp = tid >> 5, lane = tid & 31;
    int gid = lane >> 2, tig = lane & 3;
    int warpM = warp >> 2, warpN = warp & 3;
    int m_base = warpM * 32;
    int n_base = warpN * 16;
    int m0 = blockIdx.x * 64;

    // ldmatrix lane->tile mapping (tile t3 = lane>>3, row-in-tile = lane&7)
    int t3  = lane >> 3, rin = lane & 7;
    int a_row  = ((t3 & 1) << 3) + rin;        // tiles 1,3: +8 rows
    int a_colw = (t3 >> 1) << 2;               // tiles 2,3: +4 k
    int b_row  = ((t3 >> 1) << 3) + rin;       // tiles 2,3: +8 n
    int b_colw = (t3 & 1) << 2;                // tiles 1,3: +4 k

    // staging: 64 rows x 8 float4 per matrix; 256 threads -> 2 iters each
    int srow = tid >> 3, sc4 = tid & 7;

    float acc[2][2][4];
    #pragma unroll
    for (int mt = 0; mt < 2; mt++)
        #pragma unroll
        for (int nt = 0; nt < 2; nt++)
            #pragma unroll
            for (int j = 0; j < 4; j++) acc[mt][nt][j] = 0.f;

    // stage all 4 matrices (hi/lo A, hi/lo B) for chunk kc into stage sb
    #define STAGE(kc, sb) do {                                                   \
        float* _st = sm + (sb) * F_BUF;                                          \
        _Pragma("unroll")                                                        \
        for (int _i = 0; _i < 2; _i++) {                                         \
            int _row = srow + _i * 32;                                           \
            int _go = (kc) * KC + sc4 * 4;                                       \
            const float* _sah = g_Ahi + (size_t)(m0 + _row) * KDIM + _go;        \
            const float* _sal = g_Alo + (size_t)(m0 + _row) * KDIM + _go;        \
            const float* _sbh = g_Bhi + _row * KDIM + _go;                       \
            const float* _sbl = g_Blo + _row * KDIM + _go;                       \
            uint32_t _so = _row * AST + sc4 * 4;                                 \
            asm volatile("cp.async.ca.shared.global [%0], [%1], 16;"             \
                         :: "r"(smem_u32(_st + F_AHI + _so)), "l"(_sah) : "memory"); \
            asm volatile("cp.async.ca.shared.global [%0], [%1], 16;"             \
                         :: "r"(smem_u32(_st + F_ALO + _so)), "l"(_sal) : "memory"); \
            asm volatile("cp.async.ca.shared.global [%0], [%1], 16;"             \
                         :: "r"(smem_u32(_st + F_BHI + _so)), "l"(_sbh) : "memory"); \
            asm volatile("cp.async.ca.shared.global [%0], [%1], 16;"             \
                         :: "r"(smem_u32(_st + F_BLO + _so)), "l"(_sbl) : "memory"); \
        }                                                                        \
        asm volatile("cp.async.commit_group;" ::: "memory");                     \
    } while (0)

    // ---- prologue: stage chunks 0,1 ----
    STAGE(0, 0);
    STAGE(1, 1);

    for (int kc = 0; kc < NCH; kc++) {
        // oldest pending group = chunk kc (every iteration commits exactly one group)
        asm volatile("cp.async.wait_group 1;" ::: "memory");
        __syncthreads();

        int kn = kc + 2;
        if (kn < NCH) {
            STAGE(kn, kn % NSTG);           // overlaps with mma below
        } else {
            asm volatile("cp.async.commit_group;" ::: "memory");  // empty pad
        }

        // ---- mma on stage kc%NSTG: 4 k-steps ----
        float* st = sm + (kc % NSTG) * F_BUF;
        float* bAhi = st + F_AHI;
        float* bAlo = st + F_ALO;
        float* bBhi = st + F_BHI;
        float* bBlo = st + F_BLO;
        #pragma unroll
        for (int ks = 0; ks < 4; ks++) {
            int k0 = ks * 8;
            uint32_t ah[2][4], al[2][4], bh[4], bl[4];
            #pragma unroll
            for (int mt = 0; mt < 2; mt++) {
                int roff = (m_base + mt * 16 + a_row) * AST + k0 + a_colw;
                ldsm4(ah[mt], smem_u32(bAhi + roff));
                ldsm4(al[mt], smem_u32(bAlo + roff));
            }
            {
                int roff = (n_base + b_row) * AST + k0 + b_colw;
                ldsm4(bh, smem_u32(bBhi + roff));
                ldsm4(bl, smem_u32(bBlo + roff));
            }
            #pragma unroll
            for (int mt = 0; mt < 2; mt++)
                #pragma unroll
                for (int nt = 0; nt < 2; nt++) {
                    mma8(acc[mt][nt], ah[mt], &bh[nt * 2]);
                    mma8(acc[mt][nt], al[mt], &bh[nt * 2]);
                    mma8(acc[mt][nt], ah[mt], &bl[nt * 2]);
                }
        }
    }
    #undef STAGE

    // ---- epilogue: bias + store ----
    #pragma unroll
    for (int mt = 0; mt < 2; mt++) {
        int r  = m0 + m_base + mt * 16 + gid;
        int r8 = r + 8;
        #pragma unroll
        for (int nt = 0; nt < 2; nt++) {
            int c = n_base + nt * 8 + tig * 2;
            float b0 = __ldg(bias + c), b1 = __ldg(bias + c + 1);
            if (r < NP) {
                float2 v = make_float2(acc[mt][nt][0] + b0, acc[mt][nt][1] + b1);
                *(float2*)(out + (size_t)r * 64 + c) = v;
            }
            if (r8 < NP) {
                float2 v = make_float2(acc[mt][nt][2] + b0, acc[mt][nt][3] + b1);
                *(float2*)(out + (size_t)r8 * 64 + c) = v;
            }
        }
    }
}

// ===================== launch =====================
extern "C" void kernel_launch(void* const* d_in, const int* in_sizes, int n_in,
                              void* d_out, int out_size) {
    const float* feat = (const float*)d_in[0];
    const int*   recv = (const int*)d_in[1];
    const float* rp   = (const float*)d_in[2];
    const float* ws   = (const float*)d_in[3];
    const int*   snd  = (const int*)d_in[4];
    const float* ker  = (const float*)d_in[5];
    const float* bias = (const float*)d_in[6];
    float* out = (float*)d_out;

    cudaFuncSetAttribute(k_gemm, cudaFuncAttributeMaxDynamicSharedMemorySize, GEMM_SMEM);

    k_prep<<<(NPAD + 255) / 256, 256>>>(ker);
    k_fill<<<(EDG + 255) / 256, 256>>>(recv, snd, rp, ws);
    k_phase1<<<NPAD / 2, 64>>>(feat);
    k_gemm<<<NPAD / 64, 256, GEMM_SMEM>>>(bias, out);
}

// round 11
// speedup vs baseline: 1.2748x; 1.2748x over previous
#include <cuda_runtime.h>
#include <cstdint>
#include <cstddef>

// ===================== problem constants =====================
static constexpr int NP      = 50000;     // particles
static constexpr int NPAD    = 50048;     // padded to 782*64
static constexpr int EDG     = 800000;
static constexpr int CAP     = 64;        // slots per receiver (Poisson(16) tail-safe)
static constexpr int KDIM    = 512;       // folded contraction dim: 8 taps * 64 ch
static constexpr int OUTC    = 64;
static constexpr int PD      = 8;         // phase1 cp.async pipeline depth

// ===================== device scratch (no allocs allowed) =====================
__device__ int    g_deg[NPAD];
__device__ int    g_slotS[(size_t)NPAD * CAP];        // sender per slot
__device__ float4 g_wp[(size_t)NPAD * CAP * 2];       // folded weights, 2 float4 per slot
__device__ float  g_A[(size_t)NPAD * KDIM];           // folded aggregate [NPAD][512] fp32
__device__ float  g_Bhi[OUTC * KDIM];                 // tf32-hi folded kernel, [n][k]
__device__ float  g_Blo[OUTC * KDIM];                 // tf32-lo residual,      [n][k]

// ===================== helpers =====================
__device__ __forceinline__ uint32_t f2tf32(float x) {
    uint32_t r;
    asm("cvt.rna.tf32.f32 %0, %1;" : "=r"(r) : "f"(x));
    return r;
}

__device__ __forceinline__ uint32_t smem_u32(const void* p) {
    return (uint32_t)__cvta_generic_to_shared(p);
}

__device__ __forceinline__ void mma8(float* c, const uint32_t* a, const uint32_t* b) {
    asm volatile(
        "mma.sync.aligned.m16n8k8.row.col.f32.tf32.tf32.f32 "
        "{%0,%1,%2,%3}, {%4,%5,%6,%7}, {%8,%9}, {%0,%1,%2,%3};"
        : "+f"(c[0]), "+f"(c[1]), "+f"(c[2]), "+f"(c[3])
        : "r"(a[0]), "r"(a[1]), "r"(a[2]), "r"(a[3]), "r"(b[0]), "r"(b[1]));
}

__device__ __forceinline__ void ldsm4(uint32_t* r, uint32_t addr) {
    asm volatile("ldmatrix.sync.aligned.m8n8.x4.shared.b16 {%0,%1,%2,%3}, [%4];"
                 : "=r"(r[0]), "=r"(r[1]), "=r"(r[2]), "=r"(r[3]) : "r"(addr));
}

// ===================== kernel 1: zero degree counters + build folded B =====================
__global__ void k_prep(const float* __restrict__ ker) {
    int i = blockIdx.x * blockDim.x + threadIdx.x;
    if (i < NPAD) g_deg[i] = 0;
    if (i < KDIM * OUTC) {
        int n = i / KDIM;
        int k = i % KDIM;
        int t = k / 64, ic = k % 64;
        int x = t / 4, y = t % 4;
        float v;
        if (y < 2) v = ker[(((x * 2 + y) * 64 + ic) * 64) + n];
        else       v = -ker[((((3 - x) * 2 + (3 - y)) * 64 + ic) * 64) + n];
        uint32_t hb = f2tf32(v);
        float hi = __uint_as_float(hb);
        uint32_t lb = f2tf32(v - hi);
        g_Bhi[n * KDIM + k] = hi;
        g_Blo[n * KDIM + k] = __uint_as_float(lb);
    }
}

// ===================== kernel 2: bucket edges + precompute folded weights =====================
__global__ void k_fill(const int* __restrict__ recv, const int* __restrict__ snd,
                       const float* __restrict__ rp, const float* __restrict__ ws_p) {
    int e = blockIdx.x * blockDim.x + threadIdx.x;
    if (e >= EDG) return;
    int r = recv[e];
    int slot = atomicAdd(&g_deg[r], 1);
    if (slot >= CAP) return;

    float inv_ws = 1.0f / (*ws_p);
    float2 p = ((const float2*)rp)[e];
    float ux = fminf(fmaxf(p.x * inv_ws, -1.f), 1.f);
    float uy = fminf(fmaxf(p.y * inv_ws, -1.f), 1.f);
    float gx = (ux + 1.f) * 1.5f;
    float gy = (uy + 1.f) * 1.5f;
    float x0 = fminf(fmaxf(floorf(gx), 0.f), 2.f);
    float y0 = fminf(fmaxf(floorf(gy), 0.f), 2.f);
    float fx = gx - x0, fy = gy - y0;
    int x0i = (int)x0, y0i = (int)y0;
    float r2 = ux * ux + uy * uy;
    float win = fmaxf(1.f - r2, 0.f);
    win = win * win * win;

    float wx[4], wy[4];
    #pragma unroll
    for (int j = 0; j < 4; j++) {
        wx[j] = (j == x0i) ? (1.f - fx) * win : ((j == x0i + 1) ? fx * win : 0.f);
        wy[j] = (j == y0i) ? (1.f - fy)       : ((j == y0i + 1) ? fy       : 0.f);
    }
    float wf[8];
    #pragma unroll
    for (int f = 0; f < 8; f++) {
        int xf = f >> 2, yf = f & 3;
        wf[f] = wx[xf] * wy[yf] - wx[3 - xf] * wy[3 - yf];
    }
    size_t si = (size_t)r * CAP + slot;
    g_slotS[si] = snd[e];
    g_wp[si * 2 + 0] = make_float4(wf[0], wf[1], wf[2], wf[3]);
    g_wp[si * 2 + 1] = make_float4(wf[4], wf[5], wf[6], wf[7]);
}

// ===================== kernel 3: per-receiver aggregation, cp.async pipeline, unroll-4 =====================
__global__ void __launch_bounds__(64) k_phase1(const float* __restrict__ feat) {
    __shared__ float sFeat[2][PD][64];
    __shared__ float sW[2][PD][8];

    int warp = threadIdx.x >> 5, lane = threadIdx.x & 31;
    int r = blockIdx.x * 2 + warp;          // grid = NPAD/2 exactly
    int nd = min(g_deg[r], CAP);            // uniform across warp
    size_t base = (size_t)r * CAP;

    int sl = (lane < nd)      ? g_slotS[base + lane]      : 0;
    int sh = (32 + lane < nd) ? g_slotS[base + 32 + lane] : 0;

    float acc[16];
    #pragma unroll
    for (int j = 0; j < 16; j++) acc[j] = 0.f;

    #define ISSUE(e) do {                                                        \
        int _e = (e);                                                            \
        if (_e < nd) {                                                           \
            int _j = _e & (PD - 1);                                              \
            int _s = __shfl_sync(0xFFFFFFFFu, (_e < 32) ? sl : sh, _e & 31);     \
            if (lane < 16) {                                                     \
                const float4* _src = (const float4*)(feat + (size_t)_s * 64) + lane; \
                uint32_t _dst = smem_u32(&sFeat[warp][_j][lane * 4]);            \
                asm volatile("cp.async.ca.shared.global [%0], [%1], 16;"         \
                             :: "r"(_dst), "l"(_src) : "memory");                \
            } else if (lane < 18) {                                              \
                const float4* _src = &g_wp[(base + _e) * 2 + (lane - 16)];       \
                uint32_t _dst = smem_u32(&sW[warp][_j][(lane - 16) * 4]);        \
                asm volatile("cp.async.ca.shared.global [%0], [%1], 16;"         \
                             :: "r"(_dst), "l"(_src) : "memory");                \
            }                                                                    \
        }                                                                        \
        asm volatile("cp.async.commit_group;" ::: "memory");                     \
    } while (0)

    #define CONSUME(e) do {                                                      \
        int _jb = (e) & (PD - 1);                                                \
        float2 f  = *(const float2*)&sFeat[warp][_jb][lane * 2];                 \
        float4 w0 = *(const float4*)&sW[warp][_jb][0];                           \
        float4 w1 = *(const float4*)&sW[warp][_jb][4];                           \
        acc[0]  += w0.x * f.x;  acc[1]  += w0.x * f.y;                           \
        acc[2]  += w0.y * f.x;  acc[3]  += w0.y * f.y;                           \
        acc[4]  += w0.z * f.x;  acc[5]  += w0.z * f.y;                           \
        acc[6]  += w0.w * f.x;  acc[7]  += w0.w * f.y;                           \
        acc[8]  += w1.x * f.x;  acc[9]  += w1.x * f.y;                           \
        acc[10] += w1.y * f.x;  acc[11] += w1.y * f.y;                           \
        acc[12] += w1.z * f.x;  acc[13] += w1.z * f.y;                           \
        acc[14] += w1.w * f.x;  acc[15] += w1.w * f.y;                           \
    } while (0)

    #pragma unroll
    for (int j = 0; j < PD; j++) ISSUE(j);

    int e = 0;
    for (; e + 3 < nd; e += 4) {
        asm volatile("cp.async.wait_group %0;" :: "n"(PD - 4) : "memory");
        __syncwarp();
        CONSUME(e);
        CONSUME(e + 1);
        CONSUME(e + 2);
        CONSUME(e + 3);
        __syncwarp();
        ISSUE(e + PD);
        ISSUE(e + PD + 1);
        ISSUE(e + PD + 2);
        ISSUE(e + PD + 3);
    }
    if (e < nd) {
        asm volatile("cp.async.wait_group 0;" ::: "memory");
        __syncwarp();
        for (; e < nd; e++) CONSUME(e);
    }
    #undef ISSUE
    #undef CONSUME

    float* dst = g_A + (size_t)r * KDIM + 2 * lane;
    #pragma unroll
    for (int t = 0; t < 8; t++) {
        *(float2*)(dst + t * 64) = make_float2(acc[2 * t], acc[2 * t + 1]);
    }
}

// ===================== kernel 4: tf32 mma GEMM, deep-pipelined hybrid =====================
// out[NPAD(64/CTA), 64] = A[., 512] @ B^T (B stored [n][k]) + bias
// 8 warps as 2(M) x 4(N). A: LDG 2 chunks ahead -> regs -> hi/lo split STS mid-mma,
// double-buffered smem. B: 3-stage cp.async ring, wait_group 2.
static constexpr int KC  = 32;
static constexpr int AST = 36;                 // smem row stride (floats), conflict-free
static constexpr int F_ABUF = 4608;            // floats per A buffer (hi 2304 + lo 2304)
static constexpr int F_BBASE = 2 * F_ABUF;     // 9216: B stages start
static constexpr int F_BSTG = 4608;            // floats per B stage (hi 2304 + lo 2304)
static constexpr int NCH = KDIM / KC;          // 16 chunks
static constexpr int GEMM_SMEM = (F_BBASE + 3 * F_BSTG) * 4;   // 92160 bytes

__global__ void __launch_bounds__(256, 2) k_gemm(const float* __restrict__ bias,
                                                 float* __restrict__ out) {
    extern __shared__ float sm[];

    int tid = threadIdx.x;
    int warp = tid >> 5, lane = tid & 31;
    int gid = lane >> 2, tig = lane & 3;
    int warpM = warp >> 2, warpN = warp & 3;
    int m_base = warpM * 32;
    int n_base = warpN * 16;
    int m0 = blockIdx.x * 64;

    // ldmatrix lane->tile mapping
    int t3  = lane >> 3, rin = lane & 7;
    int a_row  = ((t3 & 1) << 3) + rin;
    int a_colw = (t3 >> 1) << 2;
    int b_row  = ((t3 >> 1) << 3) + rin;
    int b_colw = (t3 & 1) << 2;

    // staging: 64 rows x 8 float4; 256 threads -> 2 rows each
    int srow = tid >> 3, sc4 = tid & 7;

    float acc[2][2][4];
    #pragma unroll
    for (int mt = 0; mt < 2; mt++)
        #pragma unroll
        for (int nt = 0; nt < 2; nt++)
            #pragma unroll
            for (int j = 0; j < 4; j++) acc[mt][nt][j] = 0.f;

    const float4* Ag = (const float4*)g_A;

    #define STAGE_B(kc) do {                                                     \
        if ((kc) < NCH) {                                                        \
            float* _st = sm + F_BBASE + ((kc) % 3) * F_BSTG;                     \
            _Pragma("unroll")                                                    \
            for (int _i = 0; _i < 2; _i++) {                                     \
                int _row = srow + _i * 32;                                       \
                int _go = (kc) * KC + sc4 * 4;                                   \
                uint32_t _so = _row * AST + sc4 * 4;                             \
                asm volatile("cp.async.ca.shared.global [%0], [%1], 16;"         \
                    :: "r"(smem_u32(_st + _so)), "l"(g_Bhi + _row * KDIM + _go) : "memory"); \
                asm volatile("cp.async.ca.shared.global [%0], [%1], 16;"         \
                    :: "r"(smem_u32(_st + 2304 + _so)), "l"(g_Blo + _row * KDIM + _go) : "memory"); \
            }                                                                    \
        }                                                                        \
        asm volatile("cp.async.commit_group;" ::: "memory");                     \
    } while (0)

    #define LOAD_A_REGS(kc, av) do {                                             \
        _Pragma("unroll")                                                        \
        for (int _i = 0; _i < 2; _i++) {                                         \
            int _row = srow + _i * 32;                                           \
            (av)[_i] = Ag[(size_t)(m0 + _row) * 128 + (kc) * 8 + sc4];           \
        }                                                                        \
    } while (0)

    #define STORE_A(av, fb) do {                                                 \
        float* _ah = sm + (fb) * F_ABUF;                                         \
        float* _al = _ah + 2304;                                                 \
        _Pragma("unroll")                                                        \
        for (int _i = 0; _i < 2; _i++) {                                         \
            int _row = srow + _i * 32;                                           \
            float4 _v = (av)[_i];                                                \
            float4 _hi, _lo;                                                     \
            _hi.x = __uint_as_float(f2tf32(_v.x)); _lo.x = __uint_as_float(f2tf32(_v.x - _hi.x)); \
            _hi.y = __uint_as_float(f2tf32(_v.y)); _lo.y = __uint_as_float(f2tf32(_v.y - _hi.y)); \
            _hi.z = __uint_as_float(f2tf32(_v.z)); _lo.z = __uint_as_float(f2tf32(_v.z - _hi.z)); \
            _hi.w = __uint_as_float(f2tf32(_v.w)); _lo.w = __uint_as_float(f2tf32(_v.w - _hi.w)); \
            *(float4*)(_ah + _row * AST + sc4 * 4) = _hi;                        \
            *(float4*)(_al + _row * AST + sc4 * 4) = _lo;                        \
        }                                                                        \
    } while (0)

    // mma on A buffer `ab`, B stage of chunk kc, k-steps ks0..ks1
    #define MMA_HALF(ab, kc, ks0, ks1) do {                                      \
        float* _bA = sm + (ab) * F_ABUF;                                         \
        float* _bB = sm + F_BBASE + ((kc) % 3) * F_BSTG;                         \
        _Pragma("unroll")                                                        \
        for (int _ks = (ks0); _ks <= (ks1); _ks++) {                             \
            int _k0 = _ks * 8;                                                   \
            uint32_t _ah[2][4], _al[2][4], _bh[4], _bl[4];                       \
            _Pragma("unroll")                                                    \
            for (int _mt = 0; _mt < 2; _mt++) {                                  \
                int _ro = (m_base + _mt * 16 + a_row) * AST + _k0 + a_colw;      \
                ldsm4(_ah[_mt], smem_u32(_bA + _ro));                            \
                ldsm4(_al[_mt], smem_u32(_bA + 2304 + _ro));                     \
            }                                                                    \
            {                                                                    \
                int _ro = (n_base + b_row) * AST + _k0 + b_colw;                 \
                ldsm4(_bh, smem_u32(_bB + _ro));                                 \
                ldsm4(_bl, smem_u32(_bB + 2304 + _ro));                          \
            }                                                                    \
            _Pragma("unroll")                                                    \
            for (int _mt = 0; _mt < 2; _mt++)                                    \
                _Pragma("unroll")                                                \
                for (int _nt = 0; _nt < 2; _nt++) {                              \
                    mma8(acc[_mt][_nt], _ah[_mt], &_bh[_nt * 2]);                \
                    mma8(acc[_mt][_nt], _al[_mt], &_bh[_nt * 2]);                \
                    mma8(acc[_mt][_nt], _ah[_mt], &_bl[_nt * 2]);                \
                }                                                                \
        }                                                                        \
    } while (0)

    // ---- prologue ----
    float4 avA[2], avB[2];
    {
        float4 t0[2];
        LOAD_A_REGS(0, t0);
        STAGE_B(0);
        STAGE_B(1);
        STAGE_B(2);
        STORE_A(t0, 0);             // chunk 0 -> A buf 0
        LOAD_A_REGS(1, avB);        // chunk 1 (stored to buf 1 during iter 0)
    }
    __syncthreads();

    #pragma unroll 1
    for (int kcc = 0; kcc < NCH / 2; kcc++) {
        int kc0 = 2 * kcc, kc1 = 2 * kcc + 1;

        // ---- even iter: A buf 0, avB holds chunk kc0+1 ----
        if (kc0 + 2 < NCH) LOAD_A_REGS(kc0 + 2, avA);
        asm volatile("cp.async.wait_group 2;" ::: "memory");   // B chunk kc0 ready
        MMA_HALF(0, kc0, 0, 1);
        if (kc0 + 1 < NCH) STORE_A(avB, 1);                    // chunk kc0+1 -> buf 1
        MMA_HALF(0, kc0, 2, 3);
        __syncthreads();
        STAGE_B(kc0 + 3);

        // ---- odd iter: A buf 1, avA holds chunk kc1+1 ----
        if (kc1 + 2 < NCH) LOAD_A_REGS(kc1 + 2, avB);
        asm volatile("cp.async.wait_group 2;" ::: "memory");   // B chunk kc1 ready
        MMA_HALF(1, kc1, 0, 1);
        if (kc1 + 1 < NCH) STORE_A(avA, 0);                    // chunk kc1+1 -> buf 0
        MMA_HALF(1, kc1, 2, 3);
        __syncthreads();
        STAGE_B(kc1 + 3);
    }
    #undef STAGE_B
    #undef LOAD_A_REGS
    #undef STORE_A
    #undef MMA_HALF

    // ---- epilogue: bias + store ----
    #pragma unroll
    for (int mt = 0; mt < 2; mt++) {
        int r  = m0 + m_base + mt * 16 + gid;
        int r8 = r + 8;
        #pragma unroll
        for (int nt = 0; nt < 2; nt++) {
            int c = n_base + nt * 8 + tig * 2;
            float b0 = __ldg(bias + c), b1 = __ldg(bias + c + 1);
            if (r < NP) {
                float2 v = make_float2(acc[mt][nt][0] + b0, acc[mt][nt][1] + b1);
                *(float2*)(out + (size_t)r * 64 + c) = v;
            }
            if (r8 < NP) {
                float2 v = make_float2(acc[mt][nt][2] + b0, acc[mt][nt][3] + b1);
                *(float2*)(out + (size_t)r8 * 64 + c) = v;
            }
        }
    }
}

// ===================== launch =====================
extern "C" void kernel_launch(void* const* d_in, const int* in_sizes, int n_in,
                              void* d_out, int out_size) {
    const float* feat = (const float*)d_in[0];
    const int*   recv = (const int*)d_in[1];
    const float* rp   = (const float*)d_in[2];
    const float* ws   = (const float*)d_in[3];
    const int*   snd  = (const int*)d_in[4];
    const float* ker  = (const float*)d_in[5];
    const float* bias = (const float*)d_in[6];
    float* out = (float*)d_out;

    cudaFuncSetAttribute(k_gemm, cudaFuncAttributeMaxDynamicSharedMemorySize, GEMM_SMEM);

    k_prep<<<(NPAD + 255) / 256, 256>>>(ker);
    k_fill<<<(EDG + 255) / 256, 256>>>(recv, snd, rp, ws);
    k_phase1<<<NPAD / 2, 64>>>(feat);
    k_gemm<<<NPAD / 64, 256, GEMM_SMEM>>>(bias, out);
}

// round 13
// speedup vs baseline: 1.4914x; 1.1699x over previous
#include <cuda_runtime.h>
#include <cuda_fp16.h>
#include <cstdint>
#include <cstddef>

// ===================== problem constants =====================
static constexpr int NP      = 50000;     // particles
static constexpr int NPAD    = 50048;     // padded to 782*64
static constexpr int EDG     = 800000;
static constexpr int CAP     = 64;        // slots per receiver (Poisson(16) tail-safe)
static constexpr int KDIM    = 512;       // folded contraction dim: 8 taps * 64 ch
static constexpr int OUTC    = 64;
static constexpr int PD      = 8;         // phase1 cp.async pipeline depth

// scales (exact powers of 2): A*16, B*1024; epilogue * 2^-14
static constexpr float SA      = 16.0f;
static constexpr float SB      = 1024.0f;
static constexpr float INV_SAB = 1.0f / 16384.0f;

// ===================== device scratch (no allocs allowed) =====================
__device__ int    g_deg[NPAD];
__device__ int    g_slotS[(size_t)NPAD * CAP];        // sender per slot
__device__ float4 g_wp[(size_t)NPAD * CAP * 2];       // folded weights, 2 float4 per slot
__device__ __align__(128) __half g_Ah[(size_t)NPAD * KDIM];   // fp16-hi of A*16, [row][512]
__device__ __align__(128) __half g_Al[(size_t)NPAD * KDIM];   // fp16-lo residual
__device__ __align__(128) __half g_Bh[OUTC * KDIM];           // fp16-hi of Kfold^T*1024, [n][k]
__device__ __align__(128) __half g_Bl[OUTC * KDIM];           // fp16-lo residual

// ===================== helpers =====================
__device__ __forceinline__ uint32_t smem_u32(const void* p) {
    return (uint32_t)__cvta_generic_to_shared(p);
}

__device__ __forceinline__ void mma16(float* c, const uint32_t* a, const uint32_t* b) {
    asm volatile(
        "mma.sync.aligned.m16n8k16.row.col.f32.f16.f16.f32 "
        "{%0,%1,%2,%3}, {%4,%5,%6,%7}, {%8,%9}, {%0,%1,%2,%3};"
        : "+f"(c[0]), "+f"(c[1]), "+f"(c[2]), "+f"(c[3])
        : "r"(a[0]), "r"(a[1]), "r"(a[2]), "r"(a[3]), "r"(b[0]), "r"(b[1]));
}

__device__ __forceinline__ void ldsm4(uint32_t* r, uint32_t addr) {
    asm volatile("ldmatrix.sync.aligned.m8n8.x4.shared.b16 {%0,%1,%2,%3}, [%4];"
                 : "=r"(r[0]), "=r"(r[1]), "=r"(r[2]), "=r"(r[3]) : "r"(addr));
}

// ===================== kernel 1: zero degree counters + build folded B (fp16 hi/lo) =====================
// B layout [n][k]. k = t*64+i, t = x*4+y with x in {0,1}.
__global__ void k_prep(const float* __restrict__ ker) {
    int i = blockIdx.x * blockDim.x + threadIdx.x;
    if (i < NPAD) g_deg[i] = 0;
    if (i < KDIM * OUTC) {
        int n = i / KDIM;
        int k = i % KDIM;
        int t = k / 64, ic = k % 64;
        int x = t / 4, y = t % 4;
        float v;
        if (y < 2) v = ker[(((x * 2 + y) * 64 + ic) * 64) + n];
        else       v = -ker[((((3 - x) * 2 + (3 - y)) * 64 + ic) * 64) + n];
        float vs = v * SB;
        __half h = __float2half_rn(vs);
        __half l = __float2half_rn(vs - __half2float(h));
        g_Bh[n * KDIM + k] = h;
        g_Bl[n * KDIM + k] = l;
    }
}

// ===================== kernel 2: bucket edges + precompute folded weights =====================
__global__ void k_fill(const int* __restrict__ recv, const int* __restrict__ snd,
                       const float* __restrict__ rp, const float* __restrict__ ws_p) {
    int e = blockIdx.x * blockDim.x + threadIdx.x;
    if (e >= EDG) return;
    int r = recv[e];
    int slot = atomicAdd(&g_deg[r], 1);
    if (slot >= CAP) return;

    float inv_ws = 1.0f / (*ws_p);
    float2 p = ((const float2*)rp)[e];
    float ux = fminf(fmaxf(p.x * inv_ws, -1.f), 1.f);
    float uy = fminf(fmaxf(p.y * inv_ws, -1.f), 1.f);
    float gx = (ux + 1.f) * 1.5f;
    float gy = (uy + 1.f) * 1.5f;
    float x0 = fminf(fmaxf(floorf(gx), 0.f), 2.f);
    float y0 = fminf(fmaxf(floorf(gy), 0.f), 2.f);
    float fx = gx - x0, fy = gy - y0;
    int x0i = (int)x0, y0i = (int)y0;
    float r2 = ux * ux + uy * uy;
    float win = fmaxf(1.f - r2, 0.f);
    win = win * win * win;

    float wx[4], wy[4];
    #pragma unroll
    for (int j = 0; j < 4; j++) {
        wx[j] = (j == x0i) ? (1.f - fx) * win : ((j == x0i + 1) ? fx * win : 0.f);
        wy[j] = (j == y0i) ? (1.f - fy)       : ((j == y0i + 1) ? fy       : 0.f);
    }
    float wf[8];
    #pragma unroll
    for (int f = 0; f < 8; f++) {
        int xf = f >> 2, yf = f & 3;
        wf[f] = wx[xf] * wy[yf] - wx[3 - xf] * wy[3 - yf];
    }
    size_t si = (size_t)r * CAP + slot;
    g_slotS[si] = snd[e];
    g_wp[si * 2 + 0] = make_float4(wf[0], wf[1], wf[2], wf[3]);
    g_wp[si * 2 + 1] = make_float4(wf[4], wf[5], wf[6], wf[7]);
}

// ===================== kernel 3: per-receiver aggregation; emits fp16 hi/lo A*16 =====================
__global__ void __launch_bounds__(64) k_phase1(const float* __restrict__ feat) {
    __shared__ float sFeat[2][PD][64];
    __shared__ float sW[2][PD][8];

    int warp = threadIdx.x >> 5, lane = threadIdx.x & 31;
    int r = blockIdx.x * 2 + warp;          // grid = NPAD/2 exactly
    int nd = min(g_deg[r], CAP);            // uniform across warp
    size_t base = (size_t)r * CAP;

    int sl = (lane < nd)      ? g_slotS[base + lane]      : 0;
    int sh = (32 + lane < nd) ? g_slotS[base + 32 + lane] : 0;

    float acc[16];
    #pragma unroll
    for (int j = 0; j < 16; j++) acc[j] = 0.f;

    #define ISSUE(e) do {                                                        \
        int _e = (e);                                                            \
        if (_e < nd) {                                                           \
            int _j = _e & (PD - 1);                                              \
            int _s = __shfl_sync(0xFFFFFFFFu, (_e < 32) ? sl : sh, _e & 31);     \
            if (lane < 16) {                                                     \
                const float4* _src = (const float4*)(feat + (size_t)_s * 64) + lane; \
                uint32_t _dst = smem_u32(&sFeat[warp][_j][lane * 4]);            \
                asm volatile("cp.async.ca.shared.global [%0], [%1], 16;"         \
                             :: "r"(_dst), "l"(_src) : "memory");                \
            } else if (lane < 18) {                                              \
                const float4* _src = &g_wp[(base + _e) * 2 + (lane - 16)];       \
                uint32_t _dst = smem_u32(&sW[warp][_j][(lane - 16) * 4]);        \
                asm volatile("cp.async.ca.shared.global [%0], [%1], 16;"         \
                             :: "r"(_dst), "l"(_src) : "memory");                \
            }                                                                    \
        }                                                                        \
        asm volatile("cp.async.commit_group;" ::: "memory");                     \
    } while (0)

    #define CONSUME(e) do {                                                      \
        int _jb = (e) & (PD - 1);                                                \
        float2 f  = *(const float2*)&sFeat[warp][_jb][lane * 2];                 \
        float4 w0 = *(const float4*)&sW[warp][_jb][0];                           \
        float4 w1 = *(const float4*)&sW[warp][_jb][4];                           \
        acc[0]  += w0.x * f.x;  acc[1]  += w0.x * f.y;                           \
        acc[2]  += w0.y * f.x;  acc[3]  += w0.y * f.y;                           \
        acc[4]  += w0.z * f.x;  acc[5]  += w0.z * f.y;                           \
        acc[6]  += w0.w * f.x;  acc[7]  += w0.w * f.y;                           \
        acc[8]  += w1.x * f.x;  acc[9]  += w1.x * f.y;                           \
        acc[10] += w1.y * f.x;  acc[11] += w1.y * f.y;                           \
        acc[12] += w1.z * f.x;  acc[13] += w1.z * f.y;                           \
        acc[14] += w1.w * f.x;  acc[15] += w1.w * f.y;                           \
    } while (0)

    #pragma unroll
    for (int j = 0; j < PD; j++) ISSUE(j);

    int e = 0;
    for (; e + 3 < nd; e += 4) {
        asm volatile("cp.async.wait_group %0;" :: "n"(PD - 4) : "memory");
        __syncwarp();
        CONSUME(e);
        CONSUME(e + 1);
        CONSUME(e + 2);
        CONSUME(e + 3);
        __syncwarp();
        ISSUE(e + PD);
        ISSUE(e + PD + 1);
        ISSUE(e + PD + 2);
        ISSUE(e + PD + 3);
    }
    if (e < nd) {
        asm volatile("cp.async.wait_group 0;" ::: "memory");
        __syncwarp();
        for (; e < nd; e++) CONSUME(e);
    }
    #undef ISSUE
    #undef CONSUME

    // tail: scale by SA, split to fp16 hi/lo, store as half2 per lane pair
    __half2* dhi = (__half2*)g_Ah + (((size_t)r * KDIM) >> 1) + lane;
    __half2* dlo = (__half2*)g_Al + (((size_t)r * KDIM) >> 1) + lane;
    #pragma unroll
    for (int t = 0; t < 8; t++) {
        float v0 = acc[2 * t] * SA, v1 = acc[2 * t + 1] * SA;
        __half h0 = __float2half_rn(v0);
        __half h1 = __float2half_rn(v1);
        __half l0 = __float2half_rn(v0 - __half2float(h0));
        __half l1 = __float2half_rn(v1 - __half2float(h1));
        dhi[t * 32] = __halves2half2(h0, h1);
        dlo[t * 32] = __halves2half2(l0, l1);
    }
}

// ===================== kernel 4: fp16 3-pass mma GEMM, 4-stage cp.async multistage =====================
// out[NPAD(64/CTA), 64] = (Ah+Al)(Bh+Bl)^T * 2^-14 + bias  (drop Al*Bl)
// 8 warps as 2(M) x 4(N); warp tile 32x16; KC=32 (2 k16-steps), 16 chunks, 4 stages
static constexpr int KC    = 32;               // k (halfs) per chunk
static constexpr int HST   = 40;               // smem row stride (halfs): 80B, conflict-free
static constexpr int F_MAT = 64 * HST;         // 2560 halfs per matrix tile
static constexpr int F_STG = 4 * F_MAT;        // Ah, Al, Bh, Bl
static constexpr int NCH   = KDIM / KC;        // 16 chunks
static constexpr int GEMM_SMEM = 4 * F_STG * 2;   // 81920 bytes -> 2 CTAs/SM

__global__ void __launch_bounds__(256, 2) k_gemm(const float* __restrict__ bias,
                                                 float* __restrict__ out) {
    extern __shared__ __half smh[];

    int tid = threadIdx.x;
    int warp = tid >> 5, lane = tid & 31;
    int gid = lane >> 2, tig = lane & 3;
    int warpM = warp >> 2, warpN = warp & 3;
    int m_base = warpM * 32;
    int n_base = warpN * 16;
    int m0 = blockIdx.x * 64;

    // ldmatrix lane->tile mapping
    int t3  = lane >> 3, rin = lane & 7;
    int a_row = ((t3 & 1) << 3) + rin;         // tiles 1,3: +8 rows
    int a_k   = (t3 >> 1) << 3;                // tiles 2,3: +8 k (halfs = 16B)
    int b_row = ((t3 >> 1) << 3) + rin;        // tiles 2,3: +8 n
    int b_k   = (t3 & 1) << 3;                 // tiles 1,3: +8 k

    // staging: per matrix 64 rows x 64B; 256 threads -> 1 cp.async each
    int srow = tid >> 2, so8 = (tid & 3) * 8;  // row, half-offset (16B chunks)

    float acc[2][2][4];
    #pragma unroll
    for (int mt = 0; mt < 2; mt++)
        #pragma unroll
        for (int nt = 0; nt < 2; nt++)
            #pragma unroll
            for (int j = 0; j < 4; j++) acc[mt][nt][j] = 0.f;

    #define STAGE(kc) do {                                                       \
        if ((kc) < NCH) {                                                        \
            __half* _st = smh + ((kc) & 3) * F_STG;                              \
            int _go = (kc) * KC + so8;                                           \
            uint32_t _so = srow * HST + so8;                                     \
            asm volatile("cp.async.ca.shared.global [%0], [%1], 16;"             \
                :: "r"(smem_u32(_st + _so)),                                     \
                   "l"(g_Ah + (size_t)(m0 + srow) * KDIM + _go) : "memory");     \
            asm volatile("cp.async.ca.shared.global [%0], [%1], 16;"             \
                :: "r"(smem_u32(_st + F_MAT + _so)),                             \
                   "l"(g_Al + (size_t)(m0 + srow) * KDIM + _go) : "memory");     \
            asm volatile("cp.async.ca.shared.global [%0], [%1], 16;"             \
                :: "r"(smem_u32(_st + 2 * F_MAT + _so)),                         \
                   "l"(g_Bh + srow * KDIM + _go) : "memory");                    \
            asm volatile("cp.async.ca.shared.global [%0], [%1], 16;"             \
                :: "r"(smem_u32(_st + 3 * F_MAT + _so)),                         \
                   "l"(g_Bl + srow * KDIM + _go) : "memory");                    \
        }                                                                        \
        asm volatile("cp.async.commit_group;" ::: "memory");                     \
    } while (0)

    // ---- prologue: stage chunks 0,1,2 ----
    STAGE(0);
    STAGE(1);
    STAGE(2);

    #pragma unroll 1
    for (int kc = 0; kc < NCH; kc++) {
        asm volatile("cp.async.wait_group 2;" ::: "memory");   // chunk kc complete
        __syncthreads();
        STAGE(kc + 3);                                         // slot (kc+3)&3, free

        const __half* st  = smh + (kc & 3) * F_STG;
        const __half* pAh = st;
        const __half* pAl = st + F_MAT;
        const __half* pBh = st + 2 * F_MAT;
        const __half* pBl = st + 3 * F_MAT;

        #pragma unroll
        for (int ks = 0; ks < 2; ks++) {
            int k0 = ks * 16;
            uint32_t ah[2][4], al[2][4], bh[4], bl[4];
            #pragma unroll
            for (int mt = 0; mt < 2; mt++) {
                int off = (m_base + mt * 16 + a_row) * HST + k0 + a_k;
                ldsm4(ah[mt], smem_u32(pAh + off));
                ldsm4(al[mt], smem_u32(pAl + off));
            }
            {
                int off = (n_base + b_row) * HST + k0 + b_k;
                ldsm4(bh, smem_u32(pBh + off));
                ldsm4(bl, smem_u32(pBl + off));
            }
            #pragma unroll
            for (int mt = 0; mt < 2; mt++)
                #pragma unroll
                for (int nt = 0; nt < 2; nt++) {
                    mma16(acc[mt][nt], ah[mt], &bh[nt * 2]);
                    mma16(acc[mt][nt], al[mt], &bh[nt * 2]);
                    mma16(acc[mt][nt], ah[mt], &bl[nt * 2]);
                }
        }
    }
    #undef STAGE

    // ---- epilogue: un-scale + bias + store ----
    #pragma unroll
    for (int mt = 0; mt < 2; mt++) {
        int r  = m0 + m_base + mt * 16 + gid;
        int r8 = r + 8;
        #pragma unroll
        for (int nt = 0; nt < 2; nt++) {
            int c = n_base + nt * 8 + tig * 2;
            float b0 = __ldg(bias + c), b1 = __ldg(bias + c + 1);
            if (r < NP) {
                float2 v = make_float2(acc[mt][nt][0] * INV_SAB + b0,
                                       acc[mt][nt][1] * INV_SAB + b1);
                *(float2*)(out + (size_t)r * 64 + c) = v;
            }
            if (r8 < NP) {
                float2 v = make_float2(acc[mt][nt][2] * INV_SAB + b0,
                                       acc[mt][nt][3] * INV_SAB + b1);
                *(float2*)(out + (size_t)r8 * 64 + c) = v;
            }
        }
    }
}

// ===================== launch =====================
extern "C" void kernel_launch(void* const* d_in, const int* in_sizes, int n_in,
                              void* d_out, int out_size) {
    const float* feat = (const float*)d_in[0];
    const int*   recv = (const int*)d_in[1];
    const float* rp   = (const float*)d_in[2];
    const float* ws   = (const float*)d_in[3];
    const int*   snd  = (const int*)d_in[4];
    const float* ker  = (const float*)d_in[5];
    const float* bias = (const float*)d_in[6];
    float* out = (float*)d_out;

    cudaFuncSetAttribute(k_gemm, cudaFuncAttributeMaxDynamicSharedMemorySize, GEMM_SMEM);

    k_prep<<<(NPAD + 255) / 256, 256>>>(ker);
    k_fill<<<(EDG + 255) / 256, 256>>>(recv, snd, rp, ws);
    k_phase1<<<NPAD / 2, 64>>>(feat);
    k_gemm<<<NPAD / 64, 256, GEMM_SMEM>>>(bias, out);
}